// round 11
// baseline (speedup 1.0000x reference)
#include <cuda_runtime.h>
#include <cuda_fp16.h>
#include <cstdint>

#define NLOC  384
#define DHID  32
#define DPAIR 64
#define NCOL  (NLOC * DPAIR)   // 24576

// ---------------- scratch (static device globals; no allocations) ----------
__device__ __align__(16) __half g_Ah[NLOC * DHID];  // a fp16           [384][32]
__device__ __align__(16) __half g_Ch[NCOL * DHID];  // C*op_norm fp16   [24576][32]

// ---------------- helpers ---------------------------------------------------
__device__ __forceinline__ uint32_t smem_u32(const void* p) {
    uint32_t a;
    asm("{ .reg .u64 t; cvta.to.shared.u64 t, %1; cvt.u32.u64 %0, t; }"
        : "=r"(a) : "l"(p));
    return a;
}
__device__ __forceinline__ void ldsm_x4(uint32_t* r, uint32_t addr) {
    asm volatile("ldmatrix.sync.aligned.m8n8.x4.shared.b16 {%0,%1,%2,%3}, [%4];"
                 : "=r"(r[0]), "=r"(r[1]), "=r"(r[2]), "=r"(r[3]) : "r"(addr));
}
__device__ __forceinline__ void mma_f16(float* d, const uint32_t* a,
                                        const uint32_t* b) {
    asm volatile(
        "mma.sync.aligned.m16n8k16.row.col.f32.f16.f16.f32 "
        "{%0,%1,%2,%3}, {%4,%5,%6,%7}, {%8,%9}, {%0,%1,%2,%3};"
        : "+f"(d[0]), "+f"(d[1]), "+f"(d[2]), "+f"(d[3])
        : "r"(a[0]), "r"(a[1]), "r"(a[2]), "r"(a[3]), "r"(b[0]), "r"(b[1]));
}
__device__ __forceinline__ void stcs2(float* p, float2 v) {
    asm volatile("st.global.cs.v2.f32 [%0], {%1, %2};"
                 :: "l"(p), "f"(v.x), "f"(v.y) : "memory");
}
__device__ __forceinline__ void cp16(uint32_t dst, const void* src) {
    asm volatile("cp.async.cg.shared.global [%0], [%1], 16;"
                 :: "r"(dst), "l"(src) : "memory");
}
#define CP_COMMIT() asm volatile("cp.async.commit_group;" ::: "memory")
#define CP_WAIT0()  asm volatile("cp.async.wait_group 0;" ::: "memory")

// ---------------- kernel 12: fused A-projection + C-build -------------------
// C role (blocks 0..191):  rt = bid & 7 (W_out 256-row slice), j0 = (bid>>3)*16
// A role (blocks 192..215): n0 = (bid-192)*16
// dyn smem floats: W_t[0,9216) stride36 | m_s[9216,+2048) | W_s[11264,+4224) | b_s[15488,+512)
#define K12_WT   0
#define K12_MS   9216
#define K12_WS   11264
#define K12_BS   15488
#define K12_SMEM (16000 * 4)

__global__ __launch_bounds__(256) void k12(
        const float* __restrict__ m,
        const float* __restrict__ W_in,
        const float* __restrict__ b_in,
        const float* __restrict__ op_mask,
        const float* __restrict__ op_norm,
        const float* __restrict__ W_out)
{
    extern __shared__ float S[];
    const int tid = threadIdx.x;
    const int bid = blockIdx.x;

    if (bid >= 192) {
        // ---------------- A role ----------------
        const int n0 = (bid - 192) * 16;
        float* m_s  = S + K12_MS;
        float* Wa_s = S + K12_WS;
        #pragma unroll
        for (int i = 0; i < 2; ++i) {
            int e = tid + i * 256;
            int row = e >> 5, q = e & 31;
            ((float4*)(m_s + row * 128))[q] =
                ((const float4*)m)[(size_t)(n0 + row) * 32 + q];
        }
        #pragma unroll
        for (int i = 0; i < 16; ++i) {      // W_in rows 0..31
            int e = tid + i * 256;
            Wa_s[(e & 127) * 33 + (e >> 7)] = W_in[e];
        }
        __syncthreads();

        const float opm = op_mask[0];
        #pragma unroll
        for (int half = 0; half < 2; ++half) {
            int t = tid + half * 256;
            int rl = t >> 5, h = t & 31;
            float a0 = 0.f, a1 = 0.f;
            #pragma unroll 8
            for (int k = 0; k < 128; k += 2) {
                a0 += m_s[rl * 128 + k]     * Wa_s[k * 33 + h];
                a1 += m_s[rl * 128 + k + 1] * Wa_s[(k + 1) * 33 + h];
            }
            float v = (a0 + a1 + b_in[h]) * opm;
            g_Ah[(n0 + rl) * DHID + h] = __float2half_rn(v);
        }
        return;
    }

    // ---------------- C role: 16 j-rows per block ----------------
    const int rt = bid & 7;                 // W_out rows rt*256..+255 (row = p*32+x)
    const int j0 = (bid >> 3) * 16;         // 16 j-rows per block

    // prefetch W_out slice via cp.async (overlaps phase-1)
    {
        const uint32_t wt_b = smem_u32(S + K12_WT);
        #pragma unroll
        for (int i = 0; i < 8; ++i) {
            int e = tid + i * 256;          // 2048 chunks of 16B
            int row = e >> 3, chk = e & 7;
            cp16(wt_b + (row * 36 + chk * 4) * 4,
                 W_out + (size_t)rt * 8192 + row * 32 + chk * 4);
        }
        CP_COMMIT();
    }

    // phase 1: b for rows j0..j0+15 (two (j,y) pairs per thread)
    float* m_s  = S + K12_MS;
    float* Wb_s = S + K12_WS;
    float* b_s  = S + K12_BS;
    #pragma unroll
    for (int i = 0; i < 2; ++i) {
        int e = tid + i * 256;              // 16 rows x 32 f4
        int row = e >> 5, q = e & 31;
        ((float4*)(m_s + row * 128))[q] =
            ((const float4*)m)[(size_t)(j0 + row) * 32 + q];
    }
    #pragma unroll
    for (int i = 0; i < 16; ++i) {          // W_in rows 32..63
        int e = tid + i * 256;
        Wb_s[(e & 127) * 33 + (e >> 7)] = W_in[4096 + e];
    }
    __syncthreads();

    const float opm = op_mask[0];
    #pragma unroll
    for (int half = 0; half < 2; ++half) {
        int t = tid + half * 256;
        int j = t >> 5, y = t & 31;
        float a0 = 0.f, a1 = 0.f;
        #pragma unroll 8
        for (int k = 0; k < 128; k += 2) {
            a0 += m_s[j * 128 + k]     * Wb_s[k * 33 + y];
            a1 += m_s[j * 128 + k + 1] * Wb_s[(k + 1) * 33 + y];
        }
        b_s[j * 32 + y] = (a0 + a1 + b_in[32 + y]) * opm;
    }
    CP_WAIT0();
    __syncthreads();

    // phase 2: C rows (16 j per thread-row), pre-scaled by op_norm
    const float opn = op_norm[0];
    const float* W_t = S + K12_WT;
    float4 wq[8];
    #pragma unroll
    for (int c = 0; c < 8; ++c)
        wq[c] = *(const float4*)(W_t + tid * 36 + c * 4);
    const float* wreg = (const float*)wq;

    float acc[16];
    #pragma unroll
    for (int j = 0; j < 16; ++j) acc[j] = 0.f;
    #pragma unroll
    for (int y = 0; y < 32; ++y) {
        float w = wreg[y];
        #pragma unroll
        for (int j = 0; j < 16; ++j) acc[j] += w * b_s[j * 32 + y];
    }

    const int row = rt * 256 + tid;         // row = p*32 + x
    #pragma unroll
    for (int j = 0; j < 16; ++j)
        g_Ch[(j0 + j) * 2048 + row] = __float2half_rn(acc[j] * opn);
}

// ---------------- kernel 3: Z = A @ C^T, single-pass fp16 (R9 form) --------
// M128 x N128, 512 thr, 4x4 warps (32x32 warp tile).
// Accumulators INITIALIZED with bias*op_norm -> epilogue is pure stores.
#define SROW 40
__global__ __launch_bounds__(512, 2) void k3_gemm_mma(
        const float* __restrict__ b_out,
        const float* __restrict__ op_norm,
        float* __restrict__ out)
{
    __shared__ __align__(16) __half sA[128 * SROW];
    __shared__ __align__(16) __half sB[128 * SROW];
    __shared__ float s_bias[64];

    const int tid  = threadIdx.x;
    const int wid  = tid >> 5;
    const int lane = tid & 31;
    const int n0   = blockIdx.x * 128;
    const int m0   = blockIdx.y * 128;

    {   // A: 128 rows x 4 chunks = 512
        int row = tid >> 2, ch = tid & 3;
        *(uint4*)(sA + row * SROW + ch * 8) =
            *(const uint4*)(g_Ah + (size_t)(m0 + row) * DHID + ch * 8);
    }
    {   // B: 128 rows x 4 chunks = 512
        int row = tid >> 2, ch = tid & 3;
        *(uint4*)(sB + row * SROW + ch * 8) =
            *(const uint4*)(g_Ch + (size_t)(n0 + row) * DHID + ch * 8);
    }
    if (tid < 64) s_bias[tid] = b_out[tid] * op_norm[0];
    __syncthreads();

    const int warp_m = wid & 3;              // 32 rows
    const int warp_n = wid >> 2;             // 32 cols

    const uint32_t a_b = smem_u32(sA);
    const uint32_t b_b = smem_u32(sB);

    // ---- init accumulators with bias ----
    const int cpair = (lane & 3) * 2;
    float D[2][4][4];
    #pragma unroll
    for (int nf = 0; nf < 4; ++nf) {
        int ncl = (warp_n & 1) * 32 + nf * 8 + cpair;   // p index (n0%128==0)
        float b0 = s_bias[ncl], b1 = s_bias[ncl + 1];
        #pragma unroll
        for (int mf = 0; mf < 2; ++mf) {
            D[mf][nf][0] = b0; D[mf][nf][1] = b1;
            D[mf][nf][2] = b0; D[mf][nf][3] = b1;
        }
    }

    #pragma unroll
    for (int ks = 0; ks < 2; ++ks) {
        const int kk = ks * 16;
        uint32_t A[2][4];
        #pragma unroll
        for (int mf = 0; mf < 2; ++mf) {
            int row = warp_m * 32 + mf * 16 + (lane & 15);
            int col = kk + (lane >> 4) * 8;
            ldsm_x4(A[mf], a_b + row * (SROW * 2) + col * 2);
        }
        int brow_c = (lane & 7) + ((lane >> 4) & 1) * 8;
        int bcol   = kk + (lane & 8);
        #pragma unroll
        for (int g = 0; g < 2; ++g) {        // each x4 covers 16 cols
            int brow = warp_n * 32 + g * 16 + brow_c;
            uint32_t B[4];
            ldsm_x4(B, b_b + brow * (SROW * 2) + bcol * 2);
            #pragma unroll
            for (int mf = 0; mf < 2; ++mf) {
                mma_f16(D[mf][2 * g],     A[mf], B);
                mma_f16(D[mf][2 * g + 1], A[mf], B + 2);
            }
        }
    }

    // ---- epilogue: pure streaming stores ----
    const int rgrp = lane >> 2;
    #pragma unroll
    for (int mf = 0; mf < 2; ++mf) {
        int r0 = m0 + warp_m * 32 + mf * 16 + rgrp;
        float* p0 = out + (size_t)r0 * NCOL + n0 + warp_n * 32 + cpair;
        float* p1 = p0 + (size_t)8 * NCOL;
        #pragma unroll
        for (int nf = 0; nf < 4; ++nf) {
            stcs2(p0 + nf * 8, make_float2(D[mf][nf][0], D[mf][nf][1]));
            stcs2(p1 + nf * 8, make_float2(D[mf][nf][2], D[mf][nf][3]));
        }
    }
}

// ---------------- launch ---------------------------------------------------
extern "C" void kernel_launch(void* const* d_in, const int* in_sizes, int n_in,
                              void* d_out, int out_size)
{
    (void)in_sizes; (void)n_in; (void)out_size;
    const float* m       = (const float*)d_in[0];
    /* d_in[1] = nlist: unused by the reference */
    const float* op_mask = (const float*)d_in[2];
    const float* op_norm = (const float*)d_in[3];
    const float* W_in    = (const float*)d_in[4];
    const float* b_in    = (const float*)d_in[5];
    const float* W_out   = (const float*)d_in[6];
    const float* b_out   = (const float*)d_in[7];
    float* out = (float*)d_out;

    cudaFuncSetAttribute(k12, cudaFuncAttributeMaxDynamicSharedMemorySize, K12_SMEM);

    k12        <<<216, 256, K12_SMEM>>>(m, W_in, b_in, op_mask, op_norm, W_out);
    k3_gemm_mma<<<dim3(192, 3), 512>>>(b_out, op_norm, out);
}

// round 12
// speedup vs baseline: 1.2183x; 1.2183x over previous
#include <cuda_runtime.h>
#include <cuda_fp16.h>
#include <cstdint>

#define NLOC  384
#define DHID  32
#define DPAIR 64
#define NCOL  (NLOC * DPAIR)   // 24576

// ---------------- scratch (static device globals; no allocations) ----------
__device__ __align__(16) __half g_Ah[NLOC * DHID];  // a fp16           [384][32]
__device__ __align__(16) __half g_Ch[NCOL * DHID];  // C*op_norm fp16   [24576][32]

// ---------------- helpers ---------------------------------------------------
__device__ __forceinline__ uint32_t smem_u32(const void* p) {
    uint32_t a;
    asm("{ .reg .u64 t; cvta.to.shared.u64 t, %1; cvt.u32.u64 %0, t; }"
        : "=r"(a) : "l"(p));
    return a;
}
__device__ __forceinline__ void ldsm_x4(uint32_t* r, uint32_t addr) {
    asm volatile("ldmatrix.sync.aligned.m8n8.x4.shared.b16 {%0,%1,%2,%3}, [%4];"
                 : "=r"(r[0]), "=r"(r[1]), "=r"(r[2]), "=r"(r[3]) : "r"(addr));
}
__device__ __forceinline__ void mma_f16(float* d, const uint32_t* a,
                                        const uint32_t* b) {
    asm volatile(
        "mma.sync.aligned.m16n8k16.row.col.f32.f16.f16.f32 "
        "{%0,%1,%2,%3}, {%4,%5,%6,%7}, {%8,%9}, {%0,%1,%2,%3};"
        : "+f"(d[0]), "+f"(d[1]), "+f"(d[2]), "+f"(d[3])
        : "r"(a[0]), "r"(a[1]), "r"(a[2]), "r"(a[3]), "r"(b[0]), "r"(b[1]));
}
__device__ __forceinline__ void stcs4(float* p, float4 v) {
    asm volatile("st.global.cs.v4.f32 [%0], {%1, %2, %3, %4};"
                 :: "l"(p), "f"(v.x), "f"(v.y), "f"(v.z), "f"(v.w) : "memory");
}
__device__ __forceinline__ void cp16(uint32_t dst, const void* src) {
    asm volatile("cp.async.cg.shared.global [%0], [%1], 16;"
                 :: "r"(dst), "l"(src) : "memory");
}
#define CP_COMMIT() asm volatile("cp.async.commit_group;" ::: "memory")
#define CP_WAIT0()  asm volatile("cp.async.wait_group 0;" ::: "memory")

// ---------------- kernel 12: fused A-projection + C-build (R9 form) --------
// C role (blocks 0..383):  rt = bid & 7, j0 = (bid>>3)*8
// A role (blocks 384..407): n0 = (bid-384)*16
#define K12_WT   0
#define K12_MS   9216
#define K12_WS   11264
#define K12_BS   15488
#define K12_SMEM (16000 * 4)

__global__ __launch_bounds__(256) void k12(
        const float* __restrict__ m,
        const float* __restrict__ W_in,
        const float* __restrict__ b_in,
        const float* __restrict__ op_mask,
        const float* __restrict__ op_norm,
        const float* __restrict__ W_out)
{
    extern __shared__ float S[];
    const int tid = threadIdx.x;
    const int bid = blockIdx.x;

    if (bid >= 384) {
        // ---------------- A role ----------------
        const int n0 = (bid - 384) * 16;
        float* m_s  = S + K12_MS;
        float* Wa_s = S + K12_WS;
        #pragma unroll
        for (int i = 0; i < 2; ++i) {
            int e = tid + i * 256;
            int row = e >> 5, q = e & 31;
            ((float4*)(m_s + row * 128))[q] =
                ((const float4*)m)[(size_t)(n0 + row) * 32 + q];
        }
        #pragma unroll
        for (int i = 0; i < 16; ++i) {      // W_in rows 0..31
            int e = tid + i * 256;
            Wa_s[(e & 127) * 33 + (e >> 7)] = W_in[e];
        }
        __syncthreads();

        const float opm = op_mask[0];
        #pragma unroll
        for (int half = 0; half < 2; ++half) {
            int t = tid + half * 256;
            int rl = t >> 5, h = t & 31;
            float a0 = 0.f, a1 = 0.f;
            #pragma unroll 8
            for (int k = 0; k < 128; k += 2) {
                a0 += m_s[rl * 128 + k]     * Wa_s[k * 33 + h];
                a1 += m_s[rl * 128 + k + 1] * Wa_s[(k + 1) * 33 + h];
            }
            float v = (a0 + a1 + b_in[h]) * opm;
            g_Ah[(n0 + rl) * DHID + h] = __float2half_rn(v);
        }
        return;
    }

    // ---------------- C role: 8 j-rows per block ----------------
    const int rt = bid & 7;
    const int j0 = (bid >> 3) * 8;

    {
        const uint32_t wt_b = smem_u32(S + K12_WT);
        #pragma unroll
        for (int i = 0; i < 8; ++i) {
            int e = tid + i * 256;
            int row = e >> 3, chk = e & 7;
            cp16(wt_b + (row * 36 + chk * 4) * 4,
                 W_out + (size_t)rt * 8192 + row * 32 + chk * 4);
        }
        CP_COMMIT();
    }

    float* m_s  = S + K12_MS;
    float* Wb_s = S + K12_WS;
    float* b_s  = S + K12_BS;
    {
        int row = tid >> 5, q = tid & 31;
        ((float4*)(m_s + row * 128))[q] =
            ((const float4*)m)[(size_t)(j0 + row) * 32 + q];
    }
    #pragma unroll
    for (int i = 0; i < 16; ++i) {
        int e = tid + i * 256;
        Wb_s[(e & 127) * 33 + (e >> 7)] = W_in[4096 + e];
    }
    __syncthreads();

    {
        const int j = tid >> 5, y = tid & 31;
        float a0 = 0.f, a1 = 0.f;
        #pragma unroll 8
        for (int k = 0; k < 128; k += 2) {
            a0 += m_s[j * 128 + k]     * Wb_s[k * 33 + y];
            a1 += m_s[j * 128 + k + 1] * Wb_s[(k + 1) * 33 + y];
        }
        b_s[j * 32 + y] = (a0 + a1 + b_in[32 + y]) * op_mask[0];
    }
    CP_WAIT0();
    __syncthreads();

    const float opn = op_norm[0];
    const float* W_t = S + K12_WT;
    float4 wq[8];
    #pragma unroll
    for (int c = 0; c < 8; ++c)
        wq[c] = *(const float4*)(W_t + tid * 36 + c * 4);
    const float* wreg = (const float*)wq;

    float acc[8];
    #pragma unroll
    for (int j = 0; j < 8; ++j) acc[j] = 0.f;
    #pragma unroll
    for (int y = 0; y < 32; ++y) {
        float w = wreg[y];
        #pragma unroll
        for (int j = 0; j < 8; ++j) acc[j] += w * b_s[j * 32 + y];
    }

    const int row = rt * 256 + tid;
    #pragma unroll
    for (int j = 0; j < 8; ++j)
        g_Ch[(j0 + j) * 2048 + row] = __float2half_rn(acc[j] * opn);
}

// ---------------- kernel 3: Z = A @ C^T, warp-staged coalesced epilogue ----
// M128 x N128, 512 thr, 4x4 warps (32x32 warp tile). Single-pass fp16,
// bias*op_norm in accumulator init. Epilogue: warp-private smem stage
// (no block syncs), then full-line st.global.cs.v4.
#define SROW 40
#define OA    0
#define OB    10240
#define OBIAS 20480
#define OSTG  20736                   // 16 warps x 16 rows x 40 f32 = 40960 B
#define K3_SMEM (OSTG + 16 * 16 * 40 * 4)   // 61696

__global__ __launch_bounds__(512, 2) void k3_gemm_mma(
        const float* __restrict__ b_out,
        const float* __restrict__ op_norm,
        float* __restrict__ out)
{
    extern __shared__ char smem[];
    __half* sA    = (__half*)(smem + OA);
    __half* sB    = (__half*)(smem + OB);
    float* s_bias = (float*)(smem + OBIAS);

    const int tid  = threadIdx.x;
    const int wid  = tid >> 5;
    const int lane = tid & 31;
    const int n0   = blockIdx.x * 128;
    const int m0   = blockIdx.y * 128;

    {   // A: 128 rows x 4 chunks = 512
        int row = tid >> 2, ch = tid & 3;
        *(uint4*)(sA + row * SROW + ch * 8) =
            *(const uint4*)(g_Ah + (size_t)(m0 + row) * DHID + ch * 8);
    }
    {   // B: 128 rows x 4 chunks = 512
        int row = tid >> 2, ch = tid & 3;
        *(uint4*)(sB + row * SROW + ch * 8) =
            *(const uint4*)(g_Ch + (size_t)(n0 + row) * DHID + ch * 8);
    }
    if (tid < 64) s_bias[tid] = b_out[tid] * op_norm[0];
    __syncthreads();

    const int warp_m = wid & 3;              // 32 rows
    const int warp_n = wid >> 2;             // 32 cols

    const uint32_t a_b = smem_u32(sA);
    const uint32_t b_b = smem_u32(sB);

    // ---- init accumulators with bias ----
    const int cpair = (lane & 3) * 2;
    float D[2][4][4];
    #pragma unroll
    for (int nf = 0; nf < 4; ++nf) {
        int ncl = (warp_n & 1) * 32 + nf * 8 + cpair;   // p index (n0%128==0)
        float b0 = s_bias[ncl], b1 = s_bias[ncl + 1];
        #pragma unroll
        for (int mf = 0; mf < 2; ++mf) {
            D[mf][nf][0] = b0; D[mf][nf][1] = b1;
            D[mf][nf][2] = b0; D[mf][nf][3] = b1;
        }
    }

    #pragma unroll
    for (int ks = 0; ks < 2; ++ks) {
        const int kk = ks * 16;
        uint32_t A[2][4];
        #pragma unroll
        for (int mf = 0; mf < 2; ++mf) {
            int row = warp_m * 32 + mf * 16 + (lane & 15);
            int col = kk + (lane >> 4) * 8;
            ldsm_x4(A[mf], a_b + row * (SROW * 2) + col * 2);
        }
        int brow_c = (lane & 7) + ((lane >> 4) & 1) * 8;
        int bcol   = kk + (lane & 8);
        #pragma unroll
        for (int g = 0; g < 2; ++g) {        // each x4 covers 16 cols
            int brow = warp_n * 32 + g * 16 + brow_c;
            uint32_t B[4];
            ldsm_x4(B, b_b + brow * (SROW * 2) + bcol * 2);
            #pragma unroll
            for (int mf = 0; mf < 2; ++mf) {
                mma_f16(D[mf][2 * g],     A[mf], B);
                mma_f16(D[mf][2 * g + 1], A[mf], B + 2);
            }
        }
    }

    // ---- epilogue: warp-private stage -> full-line coalesced stores ----
    float* W = (float*)(smem + OSTG) + wid * (16 * 40);
    const int rgrp = lane >> 2;
    const int rr   = lane >> 3;          // 0..3
    const int cq   = (lane & 7) * 4;     // 0..28
    #pragma unroll
    for (int mf = 0; mf < 2; ++mf) {
        #pragma unroll
        for (int nf = 0; nf < 4; ++nf) {
            *(float2*)&W[rgrp * 40 + nf * 8 + cpair] =
                make_float2(D[mf][nf][0], D[mf][nf][1]);
            *(float2*)&W[(rgrp + 8) * 40 + nf * 8 + cpair] =
                make_float2(D[mf][nf][2], D[mf][nf][3]);
        }
        __syncwarp();
        #pragma unroll
        for (int rb = 0; rb < 4; ++rb) {
            int row = rb * 4 + rr;
            float4 v = *(const float4*)&W[row * 40 + cq];
            int gr = m0 + warp_m * 32 + mf * 16 + row;
            stcs4(out + (size_t)gr * NCOL + n0 + warp_n * 32 + cq, v);
        }
        __syncwarp();
    }
}

// ---------------- launch ---------------------------------------------------
extern "C" void kernel_launch(void* const* d_in, const int* in_sizes, int n_in,
                              void* d_out, int out_size)
{
    (void)in_sizes; (void)n_in; (void)out_size;
    const float* m       = (const float*)d_in[0];
    /* d_in[1] = nlist: unused by the reference */
    const float* op_mask = (const float*)d_in[2];
    const float* op_norm = (const float*)d_in[3];
    const float* W_in    = (const float*)d_in[4];
    const float* b_in    = (const float*)d_in[5];
    const float* W_out   = (const float*)d_in[6];
    const float* b_out   = (const float*)d_in[7];
    float* out = (float*)d_out;

    cudaFuncSetAttribute(k12, cudaFuncAttributeMaxDynamicSharedMemorySize, K12_SMEM);
    cudaFuncSetAttribute(k3_gemm_mma,
                         cudaFuncAttributeMaxDynamicSharedMemorySize, K3_SMEM);

    k12        <<<408, 256, K12_SMEM>>>(m, W_in, b_in, op_mask, op_norm, W_out);
    k3_gemm_mma<<<dim3(192, 3), 512, K3_SMEM>>>(b_out, op_norm, out);
}